// round 2
// baseline (speedup 1.0000x reference)
#include <cuda_runtime.h>
#include <cfloat>

#define NROWS   32768
#define NCTR    512
#define DIM     128
#define TOPK    10
#define TM      64
#define TN      64
#define NCHUNK  (NCTR / TN)   // 8
#define CTA     256

// Correctly-rounded squared norms (double accumulation, single fp32 rounding).
__device__ float g_c2[NCTR];
__device__ float g_x2[NROWS];

// ---------------------------------------------------------------------------
// Kernel 0: x2 and c2. One warp per row (32768 + 512 rows).
// ---------------------------------------------------------------------------
__global__ void norms_kernel(const float* __restrict__ x,
                             const float* __restrict__ ctr) {
    int warp = (blockIdx.x * blockDim.x + threadIdx.x) >> 5;
    int lane = threadIdx.x & 31;
    const float* src;
    float* dst;
    if (warp < NROWS) {
        src = x + (size_t)warp * DIM;
        dst = &g_x2[warp];
    } else if (warp < NROWS + NCTR) {
        src = ctr + (size_t)(warp - NROWS) * DIM;
        dst = &g_c2[warp - NROWS];
    } else {
        return;
    }
    float4 v = reinterpret_cast<const float4*>(src)[lane];
    double s = (double)v.x * v.x + (double)v.y * v.y
             + (double)v.z * v.z + (double)v.w * v.w;
    #pragma unroll
    for (int o = 16; o; o >>= 1) s += __shfl_xor_sync(0xffffffffu, s, o);
    if (lane == 0) *dst = (float)s;   // one correctly-rounded fp32 result
}

// ---------------------------------------------------------------------------
// Kernel 1: fused GEMM (distances) + top-10 selection + gather-write.
//
// Comparator mimics the reference bit-structure exactly:
//   d = sqrt_rn( max( fl( fl( x2 - fl(2*dot) ) + c2 ), 0 ) )
// with dot accumulated as a single sequential ascending-k FMA chain
// (matches Eigen/cuBLAS microkernel accumulation order). Equal d values
// tie-break by lower cluster index (lax.top_k stability).
//
// smem: xs[DIM][TM] (32KB)  cs[DIM][TN] (32KB)  keys[TM][NCTR] (128KB) = 192KB
// ---------------------------------------------------------------------------
__global__ void __launch_bounds__(CTA, 1)
kmeans_kernel(const float* __restrict__ x,
              const float* __restrict__ ctr,
              float* __restrict__ out) {
    extern __shared__ float smem[];
    float* xs   = smem;                  // [DIM][TM] transposed x tile
    float* cs   = xs + DIM * TM;         // [DIM][TN] transposed center chunk
    float* keys = cs + DIM * TN;         // [TM][NCTR] distance keys

    const int tid     = threadIdx.x;
    const int rowBase = blockIdx.x * TM;

    // ---- load x tile, transposed: xs[k][r] ----
    {
        int r = tid >> 2;                // 0..63
        int q = tid & 3;                 // 0..3
        const float4* src = reinterpret_cast<const float4*>(x + (size_t)(rowBase + r) * DIM);
        #pragma unroll
        for (int i = 0; i < 8; i++) {
            int k4 = q * 8 + i;
            float4 v = src[k4];
            int k = k4 * 4;
            xs[(k + 0) * TM + r] = v.x;
            xs[(k + 1) * TM + r] = v.y;
            xs[(k + 2) * TM + r] = v.z;
            xs[(k + 3) * TM + r] = v.w;
        }
    }

    const int ty = tid >> 4;             // 0..15 (rows)
    const int tx = tid & 15;             // 0..15 (centers)

    // per-thread row norms (constant across chunks)
    float x2v[4];
    #pragma unroll
    for (int i = 0; i < 4; i++) x2v[i] = g_x2[rowBase + ty * 4 + i];

    for (int chunk = 0; chunk < NCHUNK; chunk++) {
        const int cBase = chunk * TN;

        __syncthreads();  // xs ready / prev compute done before cs overwrite

        // ---- load center chunk, transposed: cs[k][c] ----
        {
            int c = tid >> 2;
            int q = tid & 3;
            const float4* src = reinterpret_cast<const float4*>(ctr + (size_t)(cBase + c) * DIM);
            #pragma unroll
            for (int i = 0; i < 8; i++) {
                int k4 = q * 8 + i;
                float4 v = src[k4];
                int k = k4 * 4;
                cs[(k + 0) * TN + c] = v.x;
                cs[(k + 1) * TN + c] = v.y;
                cs[(k + 2) * TN + c] = v.z;
                cs[(k + 3) * TN + c] = v.w;
            }
        }
        __syncthreads();

        // ---- 64x64x128 register-tiled FFMA GEMM ----
        // Single sequential FMA chain over ascending k per output element.
        float acc[4][4];
        #pragma unroll
        for (int i = 0; i < 4; i++)
            #pragma unroll
            for (int j = 0; j < 4; j++) acc[i][j] = 0.0f;

        #pragma unroll 8
        for (int k = 0; k < DIM; k++) {
            float4 a = *reinterpret_cast<const float4*>(&xs[k * TM + ty * 4]);
            float4 b = *reinterpret_cast<const float4*>(&cs[k * TN + tx * 4]);
            float av[4] = {a.x, a.y, a.z, a.w};
            float bv[4] = {b.x, b.y, b.z, b.w};
            #pragma unroll
            for (int i = 0; i < 4; i++)
                #pragma unroll
                for (int j = 0; j < 4; j++)
                    acc[i][j] = fmaf(av[i], bv[j], acc[i][j]);
        }

        // ---- d = sqrt(max((x2 - 2*dot) + c2, 0)), exact reference rounding ----
        float c2v[4];
        #pragma unroll
        for (int j = 0; j < 4; j++) c2v[j] = g_c2[cBase + tx * 4 + j];

        #pragma unroll
        for (int i = 0; i < 4; i++) {
            float4 kv;
            float d2;
            d2 = __fadd_rn(__fsub_rn(x2v[i], __fmul_rn(2.0f, acc[i][0])), c2v[0]);
            kv.x = __fsqrt_rn(fmaxf(d2, 0.0f));
            d2 = __fadd_rn(__fsub_rn(x2v[i], __fmul_rn(2.0f, acc[i][1])), c2v[1]);
            kv.y = __fsqrt_rn(fmaxf(d2, 0.0f));
            d2 = __fadd_rn(__fsub_rn(x2v[i], __fmul_rn(2.0f, acc[i][2])), c2v[2]);
            kv.z = __fsqrt_rn(fmaxf(d2, 0.0f));
            d2 = __fadd_rn(__fsub_rn(x2v[i], __fmul_rn(2.0f, acc[i][3])), c2v[3]);
            kv.w = __fsqrt_rn(fmaxf(d2, 0.0f));
            *reinterpret_cast<float4*>(&keys[(ty * 4 + i) * NCTR + cBase + tx * 4]) = kv;
        }
    }
    __syncthreads();

    // ---- per-warp top-10 selection + gather (8 rows per warp) ----
    const int warp = tid >> 5;
    const int lane = tid & 31;
    float4* out4 = reinterpret_cast<float4*>(out);

    for (int rr = 0; rr < 8; rr++) {
        const int r = warp * 8 + rr;

        // lane's 16 candidates, strided (conflict-free smem reads)
        float v[16];
        #pragma unroll
        for (int i = 0; i < 16; i++) v[i] = keys[r * NCTR + i * 32 + lane];

        // per-lane sorted top-10 (ascending key, index tie-break) via insertion
        float bv[TOPK]; int bi[TOPK];
        #pragma unroll
        for (int j = 0; j < TOPK; j++) { bv[j] = FLT_MAX; bi[j] = 0x7fffffff; }

        #pragma unroll
        for (int i = 0; i < 16; i++) {
            float val = v[i];
            int   idx = i * 32 + lane;
            if (val < bv[TOPK - 1] || (val == bv[TOPK - 1] && idx < bi[TOPK - 1])) {
                bv[TOPK - 1] = val; bi[TOPK - 1] = idx;
                #pragma unroll
                for (int j = TOPK - 1; j > 0; j--) {
                    bool sw = (bv[j] < bv[j - 1]) || (bv[j] == bv[j - 1] && bi[j] < bi[j - 1]);
                    if (sw) {
                        float tv = bv[j]; bv[j] = bv[j - 1]; bv[j - 1] = tv;
                        int   ti = bi[j]; bi[j] = bi[j - 1]; bi[j - 1] = ti;
                    }
                }
            }
        }

        // 10 rounds of warp-argmin on each lane's current head; winner pops.
        const size_t outRowBase = ((size_t)(rowBase + r)) * TOPK;
        for (int s = 0; s < TOPK; s++) {
            float mv = bv[0]; int mi = bi[0];
            #pragma unroll
            for (int o = 16; o; o >>= 1) {
                float ov = __shfl_xor_sync(0xffffffffu, mv, o);
                int   oi = __shfl_xor_sync(0xffffffffu, mi, o);
                if (ov < mv || (ov == mv && oi < mi)) { mv = ov; mi = oi; }
            }
            // gather: out[row*10+s][:] = x[mi][:]  (mi < 512, L2-resident source)
            const float4* srcRow = reinterpret_cast<const float4*>(x + (size_t)mi * DIM);
            float4 val = srcRow[lane];
            out4[(outRowBase + s) * (DIM / 4) + lane] = val;

            // pop on the (unique) owning lane
            if (mv == bv[0] && mi == bi[0]) {
                #pragma unroll
                for (int j = 0; j < TOPK - 1; j++) { bv[j] = bv[j + 1]; bi[j] = bi[j + 1]; }
                bv[TOPK - 1] = FLT_MAX; bi[TOPK - 1] = 0x7fffffff;
            }
        }
    }
}

// ---------------------------------------------------------------------------
extern "C" void kernel_launch(void* const* d_in, const int* in_sizes, int n_in,
                              void* d_out, int out_size) {
    const float* x;
    const float* ctr;
    if (in_sizes[0] == NCTR * DIM && n_in >= 2) {
        ctr = (const float*)d_in[0];
        x   = (const float*)d_in[1];
    } else {
        x   = (const float*)d_in[0];
        ctr = (const float*)d_in[1];
    }
    float* out = (float*)d_out;

    static const size_t SMEM_BYTES = (size_t)(DIM * TM + DIM * TN + TM * NCTR) * sizeof(float); // 196608
    cudaFuncSetAttribute(kmeans_kernel, cudaFuncAttributeMaxDynamicSharedMemorySize, (int)SMEM_BYTES);

    int totalWarps = NROWS + NCTR;                    // one warp per row
    int normBlocks = (totalWarps * 32 + CTA - 1) / CTA;
    norms_kernel<<<normBlocks, CTA>>>(x, ctr);
    kmeans_kernel<<<NROWS / TM, CTA, SMEM_BYTES>>>(x, ctr, out);
}

// round 3
// speedup vs baseline: 1.3155x; 1.3155x over previous
#include <cuda_runtime.h>
#include <cfloat>

#define NROWS   32768
#define NCTR    512
#define DIM     128
#define TOPK    10
#define TM      32
#define TN      64
#define NCHUNK  (NCTR / TN)   // 8
#define CTA     256

// Correctly-rounded squared norms (double accumulation, single fp32 rounding).
__device__ float g_c2[NCTR];
__device__ float g_x2[NROWS];

// ---------------------------------------------------------------------------
// Kernel 0: x2 and c2. One warp per row (32768 + 512 rows).
// ---------------------------------------------------------------------------
__global__ void norms_kernel(const float* __restrict__ x,
                             const float* __restrict__ ctr) {
    int warp = (blockIdx.x * blockDim.x + threadIdx.x) >> 5;
    int lane = threadIdx.x & 31;
    const float* src;
    float* dst;
    if (warp < NROWS) {
        src = x + (size_t)warp * DIM;
        dst = &g_x2[warp];
    } else if (warp < NROWS + NCTR) {
        src = ctr + (size_t)(warp - NROWS) * DIM;
        dst = &g_c2[warp - NROWS];
    } else {
        return;
    }
    float4 v = reinterpret_cast<const float4*>(src)[lane];
    double s = (double)v.x * v.x + (double)v.y * v.y
             + (double)v.z * v.z + (double)v.w * v.w;
    #pragma unroll
    for (int o = 16; o; o >>= 1) s += __shfl_xor_sync(0xffffffffu, s, o);
    if (lane == 0) *dst = (float)s;   // one correctly-rounded fp32 result
}

// ---------------------------------------------------------------------------
// Kernel 1: fused GEMM (distances) + top-10 selection + gather-write.
//
// Comparator mimics the reference bit-structure exactly:
//   d = sqrt_rn( max( fl( fl( x2 - fl(2*dot) ) + c2 ), 0 ) )
// with dot accumulated as a single sequential ascending-k FMA chain.
// Equal d values tie-break by lower cluster index (lax.top_k stability).
// DO NOT reassociate the FMA chain — index fidelity requires it.
//
// smem: xs[DIM][TM] 16KB + cs[DIM][TN] 32KB + keys[TM][NCTR] 64KB = 112KB
// -> 2 CTAs/SM resident (occupancy fix vs R2's 192KB/1 CTA).
// ---------------------------------------------------------------------------
__global__ void __launch_bounds__(CTA, 2)
kmeans_kernel(const float* __restrict__ x,
              const float* __restrict__ ctr,
              float* __restrict__ out) {
    extern __shared__ float smem[];
    float* xs   = smem;                  // [DIM][TM] transposed x tile
    float* cs   = xs + DIM * TM;         // [DIM][TN] transposed center chunk
    float* keys = cs + DIM * TN;         // [TM][NCTR] distance keys

    const int tid     = threadIdx.x;
    const int rowBase = blockIdx.x * TM;

    // ---- load x tile, transposed: xs[k][r] ----
    {
        int r = tid >> 3;                // 0..31
        int q = tid & 7;                 // 0..7
        const float4* src = reinterpret_cast<const float4*>(x + (size_t)(rowBase + r) * DIM);
        #pragma unroll
        for (int i = 0; i < 4; i++) {
            int k4 = q * 4 + i;          // float4 index 0..31
            float4 v = src[k4];
            int k = k4 * 4;
            xs[(k + 0) * TM + r] = v.x;
            xs[(k + 1) * TM + r] = v.y;
            xs[(k + 2) * TM + r] = v.z;
            xs[(k + 3) * TM + r] = v.w;
        }
    }

    const int ty = tid >> 4;             // 0..15 (row pairs)
    const int tx = tid & 15;             // 0..15 (center quads)

    // per-thread row norms (constant across chunks)
    float x2v[2];
    #pragma unroll
    for (int i = 0; i < 2; i++) x2v[i] = g_x2[rowBase + ty * 2 + i];

    for (int chunk = 0; chunk < NCHUNK; chunk++) {
        const int cBase = chunk * TN;

        __syncthreads();  // xs ready / prev compute done before cs overwrite

        // ---- load center chunk, transposed: cs[k][c] ----
        {
            int c = tid >> 2;            // 0..63
            int q = tid & 3;             // 0..3
            const float4* src = reinterpret_cast<const float4*>(ctr + (size_t)(cBase + c) * DIM);
            #pragma unroll
            for (int i = 0; i < 8; i++) {
                int k4 = q * 8 + i;
                float4 v = src[k4];
                int k = k4 * 4;
                cs[(k + 0) * TN + c] = v.x;
                cs[(k + 1) * TN + c] = v.y;
                cs[(k + 2) * TN + c] = v.z;
                cs[(k + 3) * TN + c] = v.w;
            }
        }
        __syncthreads();

        // ---- 32x64x128 register-tiled FFMA GEMM (2x4 per thread) ----
        float acc[2][4];
        #pragma unroll
        for (int i = 0; i < 2; i++)
            #pragma unroll
            for (int j = 0; j < 4; j++) acc[i][j] = 0.0f;

        #pragma unroll 16
        for (int k = 0; k < DIM; k++) {
            float2 a = *reinterpret_cast<const float2*>(&xs[k * TM + ty * 2]);
            float4 b = *reinterpret_cast<const float4*>(&cs[k * TN + tx * 4]);
            float av[2] = {a.x, a.y};
            float bv[4] = {b.x, b.y, b.z, b.w};
            #pragma unroll
            for (int i = 0; i < 2; i++)
                #pragma unroll
                for (int j = 0; j < 4; j++)
                    acc[i][j] = fmaf(av[i], bv[j], acc[i][j]);
        }

        // ---- d = sqrt(max((x2 - 2*dot) + c2, 0)), exact reference rounding ----
        float c2v[4];
        #pragma unroll
        for (int j = 0; j < 4; j++) c2v[j] = g_c2[cBase + tx * 4 + j];

        #pragma unroll
        for (int i = 0; i < 2; i++) {
            float4 kv;
            float d2;
            d2 = __fadd_rn(__fsub_rn(x2v[i], __fmul_rn(2.0f, acc[i][0])), c2v[0]);
            kv.x = __fsqrt_rn(fmaxf(d2, 0.0f));
            d2 = __fadd_rn(__fsub_rn(x2v[i], __fmul_rn(2.0f, acc[i][1])), c2v[1]);
            kv.y = __fsqrt_rn(fmaxf(d2, 0.0f));
            d2 = __fadd_rn(__fsub_rn(x2v[i], __fmul_rn(2.0f, acc[i][2])), c2v[2]);
            kv.z = __fsqrt_rn(fmaxf(d2, 0.0f));
            d2 = __fadd_rn(__fsub_rn(x2v[i], __fmul_rn(2.0f, acc[i][3])), c2v[3]);
            kv.w = __fsqrt_rn(fmaxf(d2, 0.0f));
            *reinterpret_cast<float4*>(&keys[(ty * 2 + i) * NCTR + cBase + tx * 4]) = kv;
        }
    }
    __syncthreads();

    // ---- per-warp top-10 selection + gather (4 rows per warp) ----
    const int warp = tid >> 5;
    const int lane = tid & 31;
    float4* out4 = reinterpret_cast<float4*>(out);

    for (int rr = 0; rr < 4; rr++) {
        const int r = warp * 4 + rr;

        // lane's 16 candidates, strided (conflict-free smem reads)
        float v[16];
        #pragma unroll
        for (int i = 0; i < 16; i++) v[i] = keys[r * NCTR + i * 32 + lane];

        // per-lane sorted top-10 (ascending key, index tie-break) via insertion
        float bv[TOPK]; int bi[TOPK];
        #pragma unroll
        for (int j = 0; j < TOPK; j++) { bv[j] = FLT_MAX; bi[j] = 0x7fffffff; }

        #pragma unroll
        for (int i = 0; i < 16; i++) {
            float val = v[i];
            int   idx = i * 32 + lane;
            if (val < bv[TOPK - 1] || (val == bv[TOPK - 1] && idx < bi[TOPK - 1])) {
                bv[TOPK - 1] = val; bi[TOPK - 1] = idx;
                #pragma unroll
                for (int j = TOPK - 1; j > 0; j--) {
                    bool sw = (bv[j] < bv[j - 1]) || (bv[j] == bv[j - 1] && bi[j] < bi[j - 1]);
                    if (sw) {
                        float tv = bv[j]; bv[j] = bv[j - 1]; bv[j - 1] = tv;
                        int   ti = bi[j]; bi[j] = bi[j - 1]; bi[j - 1] = ti;
                    }
                }
            }
        }

        // 10 rounds of warp-argmin on each lane's current head; winner pops.
        const size_t outRowBase = ((size_t)(rowBase + r)) * TOPK;
        for (int s = 0; s < TOPK; s++) {
            float mv = bv[0]; int mi = bi[0];
            #pragma unroll
            for (int o = 16; o; o >>= 1) {
                float ov = __shfl_xor_sync(0xffffffffu, mv, o);
                int   oi = __shfl_xor_sync(0xffffffffu, mi, o);
                if (ov < mv || (ov == mv && oi < mi)) { mv = ov; mi = oi; }
            }
            // gather: out[row*10+s][:] = x[mi][:]  (mi < 512, L2-resident source)
            const float4* srcRow = reinterpret_cast<const float4*>(x + (size_t)mi * DIM);
            float4 val = srcRow[lane];
            out4[(outRowBase + s) * (DIM / 4) + lane] = val;

            // pop on the (unique) owning lane
            if (mv == bv[0] && mi == bi[0]) {
                #pragma unroll
                for (int j = 0; j < TOPK - 1; j++) { bv[j] = bv[j + 1]; bi[j] = bi[j + 1]; }
                bv[TOPK - 1] = FLT_MAX; bi[TOPK - 1] = 0x7fffffff;
            }
        }
    }
}

// ---------------------------------------------------------------------------
extern "C" void kernel_launch(void* const* d_in, const int* in_sizes, int n_in,
                              void* d_out, int out_size) {
    const float* x;
    const float* ctr;
    if (in_sizes[0] == NCTR * DIM && n_in >= 2) {
        ctr = (const float*)d_in[0];
        x   = (const float*)d_in[1];
    } else {
        x   = (const float*)d_in[0];
        ctr = (const float*)d_in[1];
    }
    float* out = (float*)d_out;

    static const size_t SMEM_BYTES = (size_t)(DIM * TM + DIM * TN + TM * NCTR) * sizeof(float); // 114688
    cudaFuncSetAttribute(kmeans_kernel, cudaFuncAttributeMaxDynamicSharedMemorySize, (int)SMEM_BYTES);

    int totalWarps = NROWS + NCTR;                    // one warp per row
    int normBlocks = (totalWarps * 32 + CTA - 1) / CTA;
    norms_kernel<<<normBlocks, CTA>>>(x, ctr);
    kmeans_kernel<<<NROWS / TM, CTA, SMEM_BYTES>>>(x, ctr, out);
}

// round 4
// speedup vs baseline: 2.0724x; 1.5753x over previous
#include <cuda_runtime.h>
#include <cfloat>

#define NROWS   32768
#define NCTR    512
#define DIM     128
#define TOPK    10

#define BM 128
#define BN 128
#define BK 8
#define NSTAGE (DIM / BK)     // 16
#define GCTA 256

// Scratch (static device globals: allocation-free).
__device__ float g_c2[NCTR];
__device__ float g_x2[NROWS];
__device__ float g_keys[(size_t)NROWS * NCTR];   // 64 MB distance keys

// ---------------------------------------------------------------------------
// Kernel 0: x2 and c2, correctly rounded (double accumulation). 1 warp/row.
// ---------------------------------------------------------------------------
__global__ void norms_kernel(const float* __restrict__ x,
                             const float* __restrict__ ctr) {
    int warp = (blockIdx.x * blockDim.x + threadIdx.x) >> 5;
    int lane = threadIdx.x & 31;
    const float* src;
    float* dst;
    if (warp < NROWS) {
        src = x + (size_t)warp * DIM;
        dst = &g_x2[warp];
    } else if (warp < NROWS + NCTR) {
        src = ctr + (size_t)(warp - NROWS) * DIM;
        dst = &g_c2[warp - NROWS];
    } else {
        return;
    }
    float4 v = reinterpret_cast<const float4*>(src)[lane];
    double s = (double)v.x * v.x + (double)v.y * v.y
             + (double)v.z * v.z + (double)v.w * v.w;
    #pragma unroll
    for (int o = 16; o; o >>= 1) s += __shfl_xor_sync(0xffffffffu, s, o);
    if (lane == 0) *dst = (float)s;
}

// ---------------------------------------------------------------------------
// Kernel 1: 32768x512x128 SGEMM -> distance keys.
//
// Block 128x128, thread tile 8x8 (1 B smem / FMA -> half the crossbar),
// BK=8 double-buffered smem (16 KB), 2 CTAs/SM.
//
// Each key: d = sqrt_rn( max( fl( fl( x2 - fl(2*dot) ) + c2 ), 0 ) ) with dot
// as ONE sequential ascending-k FMA chain per element (index-fidelity
// invariant — do not reassociate / split K).
// ---------------------------------------------------------------------------
__global__ void __launch_bounds__(GCTA, 2)
gemm_keys_kernel(const float* __restrict__ x,
                 const float* __restrict__ ctr) {
    __shared__ float as[2][BK][BM];
    __shared__ float bs[2][BK][BN];

    const int tid    = threadIdx.x;
    const int rowBlk = blockIdx.x * BM;
    const int ctrBlk = blockIdx.y * BN;

    // loader: thread -> (row/ctr lr, k-quad lq); one float4 of A and B / stage
    const int lr = tid >> 1;          // 0..127
    const int lq = tid & 1;           // 0..1
    const float4* xsrc = reinterpret_cast<const float4*>(x   + (size_t)(rowBlk + lr) * DIM);
    const float4* csrc = reinterpret_cast<const float4*>(ctr + (size_t)(ctrBlk + lr) * DIM);

    const int tx = tid & 15;          // ctr groups
    const int ty = tid >> 4;          // row groups

    float acc[8][8];
    #pragma unroll
    for (int i = 0; i < 8; i++)
        #pragma unroll
        for (int j = 0; j < 8; j++) acc[i][j] = 0.0f;

    // prologue: stage 0
    float4 av = xsrc[lq];
    float4 bv = csrc[lq];
    as[0][lq * 4 + 0][lr] = av.x; as[0][lq * 4 + 1][lr] = av.y;
    as[0][lq * 4 + 2][lr] = av.z; as[0][lq * 4 + 3][lr] = av.w;
    bs[0][lq * 4 + 0][lr] = bv.x; bs[0][lq * 4 + 1][lr] = bv.y;
    bs[0][lq * 4 + 2][lr] = bv.z; bs[0][lq * 4 + 3][lr] = bv.w;
    __syncthreads();

    for (int s = 0; s < NSTAGE; s++) {
        const int buf = s & 1;
        if (s + 1 < NSTAGE) {                 // prefetch next slab to regs
            av = xsrc[(s + 1) * 2 + lq];
            bv = csrc[(s + 1) * 2 + lq];
        }

        #pragma unroll
        for (int k = 0; k < BK; k++) {
            float a[8], b[8];
            *reinterpret_cast<float4*>(&a[0]) = *reinterpret_cast<const float4*>(&as[buf][k][ty * 8]);
            *reinterpret_cast<float4*>(&a[4]) = *reinterpret_cast<const float4*>(&as[buf][k][ty * 8 + 4]);
            *reinterpret_cast<float4*>(&b[0]) = *reinterpret_cast<const float4*>(&bs[buf][k][tx * 8]);
            *reinterpret_cast<float4*>(&b[4]) = *reinterpret_cast<const float4*>(&bs[buf][k][tx * 8 + 4]);
            #pragma unroll
            for (int i = 0; i < 8; i++)
                #pragma unroll
                for (int j = 0; j < 8; j++)
                    acc[i][j] = fmaf(a[i], b[j], acc[i][j]);
        }

        if (s + 1 < NSTAGE) {
            const int nbuf = 1 - buf;
            as[nbuf][lq * 4 + 0][lr] = av.x; as[nbuf][lq * 4 + 1][lr] = av.y;
            as[nbuf][lq * 4 + 2][lr] = av.z; as[nbuf][lq * 4 + 3][lr] = av.w;
            bs[nbuf][lq * 4 + 0][lr] = bv.x; bs[nbuf][lq * 4 + 1][lr] = bv.y;
            bs[nbuf][lq * 4 + 2][lr] = bv.z; bs[nbuf][lq * 4 + 3][lr] = bv.w;
            __syncthreads();
        }
    }

    // epilogue: d = sqrt(max((x2 - 2*dot) + c2, 0)), exact reference rounding
    float x2v[8], c2v[8];
    #pragma unroll
    for (int i = 0; i < 8; i++) x2v[i] = g_x2[rowBlk + ty * 8 + i];
    #pragma unroll
    for (int j = 0; j < 8; j++) c2v[j] = g_c2[ctrBlk + tx * 8 + j];

    #pragma unroll
    for (int i = 0; i < 8; i++) {
        const size_t rowOff = (size_t)(rowBlk + ty * 8 + i) * NCTR + ctrBlk + tx * 8;
        #pragma unroll
        for (int g = 0; g < 2; g++) {
            float4 kv;
            float d2;
            d2 = __fadd_rn(__fsub_rn(x2v[i], __fmul_rn(2.0f, acc[i][g*4+0])), c2v[g*4+0]);
            kv.x = __fsqrt_rn(fmaxf(d2, 0.0f));
            d2 = __fadd_rn(__fsub_rn(x2v[i], __fmul_rn(2.0f, acc[i][g*4+1])), c2v[g*4+1]);
            kv.y = __fsqrt_rn(fmaxf(d2, 0.0f));
            d2 = __fadd_rn(__fsub_rn(x2v[i], __fmul_rn(2.0f, acc[i][g*4+2])), c2v[g*4+2]);
            kv.z = __fsqrt_rn(fmaxf(d2, 0.0f));
            d2 = __fadd_rn(__fsub_rn(x2v[i], __fmul_rn(2.0f, acc[i][g*4+3])), c2v[g*4+3]);
            kv.w = __fsqrt_rn(fmaxf(d2, 0.0f));
            *reinterpret_cast<float4*>(&g_keys[rowOff + g * 4]) = kv;
        }
    }
}

// ---------------------------------------------------------------------------
// Kernel 2: per-row top-10 selection + gather. One warp per row.
// ---------------------------------------------------------------------------
__global__ void __launch_bounds__(256)
select_kernel(const float* __restrict__ x, float* __restrict__ out) {
    const int row  = blockIdx.x * 8 + (threadIdx.x >> 5);
    const int lane = threadIdx.x & 31;

    // 16 candidates per lane, coalesced float4 reads
    const float4* krow = reinterpret_cast<const float4*>(g_keys + (size_t)row * NCTR);
    float v[16];
    #pragma unroll
    for (int q = 0; q < 4; q++) {
        float4 t = krow[q * 32 + lane];
        v[q * 4 + 0] = t.x; v[q * 4 + 1] = t.y;
        v[q * 4 + 2] = t.z; v[q * 4 + 3] = t.w;
    }

    // per-lane sorted top-10 (ascending key, index tie-break) via insertion
    float bv[TOPK]; int bi[TOPK];
    #pragma unroll
    for (int j = 0; j < TOPK; j++) { bv[j] = FLT_MAX; bi[j] = 0x7fffffff; }

    #pragma unroll
    for (int q = 0; q < 4; q++) {
        #pragma unroll
        for (int j4 = 0; j4 < 4; j4++) {
            float val = v[q * 4 + j4];
            int   idx = q * 128 + lane * 4 + j4;
            if (val < bv[TOPK - 1] || (val == bv[TOPK - 1] && idx < bi[TOPK - 1])) {
                bv[TOPK - 1] = val; bi[TOPK - 1] = idx;
                #pragma unroll
                for (int j = TOPK - 1; j > 0; j--) {
                    bool sw = (bv[j] < bv[j - 1]) || (bv[j] == bv[j - 1] && bi[j] < bi[j - 1]);
                    if (sw) {
                        float tv = bv[j]; bv[j] = bv[j - 1]; bv[j - 1] = tv;
                        int   ti = bi[j]; bi[j] = bi[j - 1]; bi[j - 1] = ti;
                    }
                }
            }
        }
    }

    // 10 warp-argmin rounds; winner pops; fused gather write.
    float4* out4 = reinterpret_cast<float4*>(out);
    const size_t outRowBase = (size_t)row * TOPK;
    for (int s = 0; s < TOPK; s++) {
        float mv = bv[0]; int mi = bi[0];
        #pragma unroll
        for (int o = 16; o; o >>= 1) {
            float ov = __shfl_xor_sync(0xffffffffu, mv, o);
            int   oi = __shfl_xor_sync(0xffffffffu, mi, o);
            if (ov < mv || (ov == mv && oi < mi)) { mv = ov; mi = oi; }
        }
        // gather: out[row*10+s][:] = x[mi][:]  (mi < 512, L2-resident source)
        const float4* srcRow = reinterpret_cast<const float4*>(x + (size_t)mi * DIM);
        out4[(outRowBase + s) * (DIM / 4) + lane] = srcRow[lane];

        if (mv == bv[0] && mi == bi[0]) {
            #pragma unroll
            for (int j = 0; j < TOPK - 1; j++) { bv[j] = bv[j + 1]; bi[j] = bi[j + 1]; }
            bv[TOPK - 1] = FLT_MAX; bi[TOPK - 1] = 0x7fffffff;
        }
    }
}

// ---------------------------------------------------------------------------
extern "C" void kernel_launch(void* const* d_in, const int* in_sizes, int n_in,
                              void* d_out, int out_size) {
    const float* x;
    const float* ctr;
    if (in_sizes[0] == NCTR * DIM && n_in >= 2) {
        ctr = (const float*)d_in[0];
        x   = (const float*)d_in[1];
    } else {
        x   = (const float*)d_in[0];
        ctr = (const float*)d_in[1];
    }
    float* out = (float*)d_out;

    int totalWarps = NROWS + NCTR;
    int normBlocks = (totalWarps * 32 + 255) / 256;
    norms_kernel<<<normBlocks, 256>>>(x, ctr);

    dim3 ggrid(NROWS / BM, NCTR / BN);        // 256 x 4
    gemm_keys_kernel<<<ggrid, GCTA>>>(x, ctr);

    select_kernel<<<NROWS / 8, 256>>>(x, out);
}